// round 5
// baseline (speedup 1.0000x reference)
#include <cuda_runtime.h>
#include <math.h>
#include <stdint.h>

// Problem constants (per reference setup_inputs)
#define BB 8
#define NN 4096
#define CC 256
#define HN 8
#define DH 32

// kv scratch: [b][h][e][d] and precomputed 1/softplus(scale)
__device__ float g_kv[BB * HN * DH * DH];
__device__ float g_rscale[CC];

// ---------------- helpers ----------------

__device__ __forceinline__ float2 ffma2(float2 a, float2 b, float2 c) {
    union U { float2 f; unsigned long long u; };
    U A, B_, C_, D;
    A.f = a; B_.f = b; C_.f = c;
    asm("fma.rn.f32x2 %0, %1, %2, %3;" : "=l"(D.u) : "l"(A.u), "l"(B_.u), "l"(C_.u));
    return D.f;
}

__device__ __forceinline__ float leaky1(float x) { return fmaxf(x, 0.1f * x); }

__device__ __forceinline__ float4 prep4(float4 a, float4 p, float4 rs) {
    float4 r;
    r.x = leaky1(a.x + p.x) * rs.x;
    r.y = leaky1(a.y + p.y) * rs.y;
    r.z = leaky1(a.z + p.z) * rs.z;
    r.w = leaky1(a.w + p.w) * rs.w;
    return r;
}

__device__ __forceinline__ float dot4(float4 a, float4 b) {
    return a.x * b.x + a.y * b.y + a.z * b.z + a.w * b.w;
}

__device__ __forceinline__ float4 cube4(float4 a) {
    float4 r;
    r.x = a.x * a.x * a.x; r.y = a.y * a.y * a.y;
    r.z = a.z * a.z * a.z; r.w = a.w * a.w * a.w;
    return r;
}

__device__ __forceinline__ float4 mul4s(float4 a, float s) {
    float4 r; r.x = a.x * s; r.y = a.y * s; r.z = a.z * s; r.w = a.w * s; return r;
}

__device__ __forceinline__ void cp_async16(uint32_t saddr, const void* g) {
    asm volatile("cp.async.cg.shared.global [%0], [%1], 16;" :: "r"(saddr), "l"(g));
}
#define CP_COMMIT() asm volatile("cp.async.commit_group;")
#define CP_WAIT0()  asm volatile("cp.async.wait_group 0;")

__device__ __forceinline__ uint32_t s2u(const void* p) {
    return (uint32_t)__cvta_generic_to_shared(p);
}

// feature transform of one row held warp-wide in registers; writes focused row to smem
__device__ __forceinline__ void transform_store(
    float4 a0, float4 a1, float4 p0, float4 p1,
    float4 rs0, float4 rs1, float* qrow, int lane, float extra)
{
    float4 t0 = prep4(a0, p0, rs0);
    float4 t1 = prep4(a1, p1, rs1);
    float s2 = dot4(t0, t0) + dot4(t1, t1);
    float4 u0 = cube4(t0), u1 = cube4(t1);
    float s6 = dot4(u0, u0) + dot4(u1, u1);
#pragma unroll
    for (int m = 16; m; m >>= 1) {
        s2 += __shfl_xor_sync(0xffffffffu, s2, m);
        s6 += __shfl_xor_sync(0xffffffffu, s6, m);
    }
    const float f = (s6 > 0.f) ? sqrtf(s2 / s6) * extra : 0.f;
    reinterpret_cast<float4*>(qrow)[lane]      = mul4s(u0, f);
    reinterpret_cast<float4*>(qrow)[32 + lane] = mul4s(u1, f);
}

// ---------------- kernel 0: zero kv scratch + precompute 1/softplus(scale) ----------------

__global__ void setup_kernel(const float* __restrict__ scale) {
    int i = blockIdx.x * blockDim.x + threadIdx.x;
    reinterpret_cast<float4*>(g_kv)[i] = make_float4(0.f, 0.f, 0.f, 0.f);
    if (blockIdx.x == 0) {
        float s = scale[threadIdx.x];
        g_rscale[threadIdx.x] = 1.0f / log1pf(expf(s));
    }
}

// ---------------- kernel 1: fused k-feature + kv accumulation ----------------
// grid (64, B) = 512 blocks, 256 threads (8 warps), 3 CTAs/SM target.
// v staged via cp.async (no registers); k+pe register-prefetched across the
// accumulate; double-buffered smem.

__global__ void __launch_bounds__(256, 3) kv_kernel(
    const float* __restrict__ k, const float* __restrict__ v,
    const float* __restrict__ pe2)
{
    __shared__ float ks[2][8 * 256];
    __shared__ float vsm[2][8 * 256];

    const int tid = threadIdx.x;
    const int w = tid >> 5;
    const int lane = tid & 31;
    const int b = blockIdx.y;
    const int n0 = blockIdx.x * 64;

    const float4* rsg = reinterpret_cast<const float4*>(g_rscale);
    const float4 rs0 = rsg[lane];
    const float4 rs1 = rsg[32 + lane];

    float2 acc[16];
#pragma unroll
    for (int j = 0; j < 16; j++) acc[j] = make_float2(0.f, 0.f);

    // prologue: cp.async v group 0, LDG k/pe group 0
#pragma unroll
    for (int i = 0; i < 2; i++) {
        int idx = i * 256 + tid;
        int r = idx >> 6, c = idx & 63;
        cp_async16(s2u(&vsm[0][r * 256 + c * 4]),
                   v + ((size_t)b * NN + n0 + r) * CC + c * 4);
    }
    CP_COMMIT();

    float4 ka0, ka1, pa0, pa1;
    {
        const int row = n0 + w;
        const float4* kg = reinterpret_cast<const float4*>(k + ((size_t)b * NN + row) * CC);
        const float4* pg = reinterpret_cast<const float4*>(pe2 + (size_t)row * CC);
        ka0 = kg[lane]; ka1 = kg[32 + lane];
        pa0 = pg[lane]; pa1 = pg[32 + lane];
    }

#pragma unroll
    for (int g = 0; g < 8; g++) {
        const int buf = g & 1;

        transform_store(ka0, ka1, pa0, pa1, rs0, rs1, &ks[buf][w * 256], lane, 1.0f);
        CP_WAIT0();
        __syncthreads();

        if (g < 7) {
            const int gn = g + 1;
#pragma unroll
            for (int i = 0; i < 2; i++) {
                int idx = i * 256 + tid;
                int r = idx >> 6, c = idx & 63;
                cp_async16(s2u(&vsm[buf ^ 1][r * 256 + c * 4]),
                           v + ((size_t)b * NN + n0 + gn * 8 + r) * CC + c * 4);
            }
            CP_COMMIT();
            const int row = n0 + gn * 8 + w;
            const float4* kg = reinterpret_cast<const float4*>(k + ((size_t)b * NN + row) * CC);
            const float4* pg = reinterpret_cast<const float4*>(pe2 + (size_t)row * CC);
            ka0 = kg[lane]; ka1 = kg[32 + lane];
            pa0 = pg[lane]; pa1 = pg[32 + lane];
        }

#pragma unroll
        for (int r = 0; r < 8; r++) {
            const float kd = ks[buf][r * 256 + w * 32 + lane];
            const float2 k2 = make_float2(kd, kd);
            const float4* vp = reinterpret_cast<const float4*>(&vsm[buf][r * 256 + w * 32]);
#pragma unroll
            for (int j = 0; j < 8; j++) {
                float4 vv = vp[j];
                acc[2 * j]     = ffma2(k2, make_float2(vv.x, vv.y), acc[2 * j]);
                acc[2 * j + 1] = ffma2(k2, make_float2(vv.z, vv.w), acc[2 * j + 1]);
            }
        }
    }

    float* base = g_kv + ((size_t)b * HN + w) * (DH * DH);       // [e][d]
#pragma unroll
    for (int j = 0; j < 16; j++) {
        atomicAdd(base + (2 * j) * DH + lane,     acc[j].x);
        atomicAdd(base + (2 * j + 1) * DH + lane, acc[j].y);
    }
}

// ---------------- kernel 2: q-feature + x = qf@kv + leaky(v@W^T + b) ----------------
// 512 threads (16 warps: warp = (head, e-half)), grid (32, 8). 4 tiles of 32
// rows per block. Double-buffered staging; next tile's v via cp.async, next
// tile's q+pe register-prefetched and transformed in the middle of the e-loop.

#define RP 260
#define TILE_F (32 * RP)
#define SMEM_FLOATS (4 * TILE_F + HN * DH * DH + DH * DH + DH)
#define SMEM_BYTES (SMEM_FLOATS * 4)

__global__ void __launch_bounds__(512) out_kernel(
    const float* __restrict__ q, const float* __restrict__ v,
    const float* __restrict__ pe1,
    const float* __restrict__ wconv, const float* __restrict__ bconv,
    float* __restrict__ out)
{
    extern __shared__ float sm[];
    float* sqf[2] = { sm,              sm + TILE_F };
    float* svs[2] = { sm + 2 * TILE_F, sm + 3 * TILE_F };
    float* skv = sm + 4 * TILE_F;      // [h][e][d] 8192
    float* sW  = skv + HN * DH * DH;   // [o][d] 1024
    float* sb  = sW + DH * DH;         // 32

    const int tid = threadIdx.x;
    const int W = tid >> 5;
    const int lane = tid & 31;
    const int h = W >> 1;
    const int eh = W & 1;
    const int b = blockIdx.y;

    // stage kv[b], W, bias
    {
        const float4* kvg = reinterpret_cast<const float4*>(g_kv + (size_t)b * HN * DH * DH);
        float4* s4 = reinterpret_cast<float4*>(skv);
#pragma unroll
        for (int i = 0; i < 4; i++) s4[i * 512 + tid] = kvg[i * 512 + tid];
        if (tid < 256) reinterpret_cast<float4*>(sW)[tid] = reinterpret_cast<const float4*>(wconv)[tid];
        if (tid < 32) sb[tid] = bconv[tid];
    }

    const float4* rsg = reinterpret_cast<const float4*>(g_rscale);
    const float4 rs0 = rsg[lane];
    const float4 rs1 = rsg[32 + lane];

    const int tile0 = blockIdx.x * 4;
    const float invN = 1.0f / (float)NN;

    // prologue: stage tile 0
    {
        const int n0 = tile0 * 32;
#pragma unroll
        for (int i = 0; i < 4; i++) {
            int idx = i * 512 + tid;
            int r = idx >> 6, c = idx & 63;
            cp_async16(s2u(&svs[0][r * RP + c * 4]),
                       v + ((size_t)b * NN + n0 + r) * CC + c * 4);
        }
        CP_COMMIT();
#pragma unroll
        for (int i = 0; i < 2; i++) {
            const int rl = 2 * W + i;
            const int row = n0 + rl;
            const float4* qg = reinterpret_cast<const float4*>(q + ((size_t)b * NN + row) * CC);
            const float4* pg = reinterpret_cast<const float4*>(pe1 + (size_t)row * CC);
            float4 a0 = qg[lane], a1 = qg[32 + lane];
            float4 p0 = pg[lane], p1 = pg[32 + lane];
            transform_store(a0, a1, p0, p1, rs0, rs1, &sqf[0][rl * RP], lane, invN);
        }
        CP_WAIT0();
        __syncthreads();
    }

    for (int it = 0; it < 4; it++) {
        const int buf = it & 1;
        const int n0 = (tile0 + it) * 32;
        const int n1 = n0 + 32;
        const bool more = (it < 3);

        // issue next tile's v copy
        if (more) {
#pragma unroll
            for (int i = 0; i < 4; i++) {
                int idx = i * 512 + tid;
                int r = idx >> 6, c = idx & 63;
                cp_async16(s2u(&svs[buf ^ 1][r * RP + c * 4]),
                           v + ((size_t)b * NN + n1 + r) * CC + c * 4);
            }
            CP_COMMIT();
        }

        // load this tile's row (n = n0+lane) for head h into registers
        float2 q2[16], v2[16];
        {
            const float4* qp = reinterpret_cast<const float4*>(sqf[buf] + lane * RP + h * DH);
            const float4* vp = reinterpret_cast<const float4*>(svs[buf] + lane * RP + h * DH);
#pragma unroll
            for (int j = 0; j < 8; j++) {
                float4 t = qp[j];
                q2[2 * j]     = make_float2(t.x, t.y);
                q2[2 * j + 1] = make_float2(t.z, t.w);
                float4 s = vp[j];
                v2[2 * j]     = make_float2(s.x, s.y);
                v2[2 * j + 1] = make_float2(s.z, s.w);
            }
        }

        // prefetch next tile's first staged row (this warp stages rows 2W, 2W+1)
        float4 qa0, qa1, pa0, pa1;
        if (more) {
            const int row = n1 + 2 * W;
            const float4* qg = reinterpret_cast<const float4*>(q + ((size_t)b * NN + row) * CC);
            const float4* pg = reinterpret_cast<const float4*>(pe1 + (size_t)row * CC);
            qa0 = qg[lane]; qa1 = qg[32 + lane];
            pa0 = pg[lane]; pa1 = pg[32 + lane];
        }

        float* outb = out + ((size_t)b * CC + h * DH + eh * 16) * NN + n0 + lane;

        // e-loop, first half (e = eh*16 + j, j = 0..7)
#pragma unroll
        for (int j = 0; j < 8; j++) {
            const int e = eh * 16 + j;
            const float4* kp = reinterpret_cast<const float4*>(skv + h * (DH * DH) + e * DH);
            const float4* wp = reinterpret_cast<const float4*>(sW + e * DH);
            float2 ax0 = make_float2(0.f, 0.f), ax1 = make_float2(0.f, 0.f);
            float2 ac0 = make_float2(0.f, 0.f), ac1 = make_float2(0.f, 0.f);
#pragma unroll
            for (int jj = 0; jj < 4; jj++) {
                float4 kd0 = kp[2 * jj], kd1 = kp[2 * jj + 1];
                float4 wd0 = wp[2 * jj], wd1 = wp[2 * jj + 1];
                ax0 = ffma2(q2[4 * jj],     make_float2(kd0.x, kd0.y), ax0);
                ax1 = ffma2(q2[4 * jj + 1], make_float2(kd0.z, kd0.w), ax1);
                ax0 = ffma2(q2[4 * jj + 2], make_float2(kd1.x, kd1.y), ax0);
                ax1 = ffma2(q2[4 * jj + 3], make_float2(kd1.z, kd1.w), ax1);
                ac0 = ffma2(v2[4 * jj],     make_float2(wd0.x, wd0.y), ac0);
                ac1 = ffma2(v2[4 * jj + 1], make_float2(wd0.z, wd0.w), ac1);
                ac0 = ffma2(v2[4 * jj + 2], make_float2(wd1.x, wd1.y), ac0);
                ac1 = ffma2(v2[4 * jj + 3], make_float2(wd1.z, wd1.w), ac1);
            }
            float xv = (ax0.x + ax0.y) + (ax1.x + ax1.y);
            float cv = leaky1((ac0.x + ac0.y) + (ac1.x + ac1.y) + sb[e]);
            outb[(size_t)j * NN] = xv + cv;
        }

        // mid-loop: transform prefetched row A, prefetch row B
        if (more) {
            transform_store(qa0, qa1, pa0, pa1, rs0, rs1,
                            &sqf[buf ^ 1][(2 * W) * RP], lane, invN);
            const int row = n1 + 2 * W + 1;
            const float4* qg = reinterpret_cast<const float4*>(q + ((size_t)b * NN + row) * CC);
            const float4* pg = reinterpret_cast<const float4*>(pe1 + (size_t)row * CC);
            qa0 = qg[lane]; qa1 = qg[32 + lane];
            pa0 = pg[lane]; pa1 = pg[32 + lane];
        }

        // e-loop, second half (j = 8..15)
#pragma unroll
        for (int j = 8; j < 16; j++) {
            const int e = eh * 16 + j;
            const float4* kp = reinterpret_cast<const float4*>(skv + h * (DH * DH) + e * DH);
            const float4* wp = reinterpret_cast<const float4*>(sW + e * DH);
            float2 ax0 = make_float2(0.f, 0.f), ax1 = make_float2(0.f, 0.f);
            float2 ac0 = make_float2(0.f, 0.f), ac1 = make_float2(0.f, 0.f);
#pragma unroll
            for (int jj = 0; jj < 4; jj++) {
                float4 kd0 = kp[2 * jj], kd1 = kp[2 * jj + 1];
                float4 wd0 = wp[2 * jj], wd1 = wp[2 * jj + 1];
                ax0 = ffma2(q2[4 * jj],     make_float2(kd0.x, kd0.y), ax0);
                ax1 = ffma2(q2[4 * jj + 1], make_float2(kd0.z, kd0.w), ax1);
                ax0 = ffma2(q2[4 * jj + 2], make_float2(kd1.x, kd1.y), ax0);
                ax1 = ffma2(q2[4 * jj + 3], make_float2(kd1.z, kd1.w), ax1);
                ac0 = ffma2(v2[4 * jj],     make_float2(wd0.x, wd0.y), ac0);
                ac1 = ffma2(v2[4 * jj + 1], make_float2(wd0.z, wd0.w), ac1);
                ac0 = ffma2(v2[4 * jj + 2], make_float2(wd1.x, wd1.y), ac0);
                ac1 = ffma2(v2[4 * jj + 3], make_float2(wd1.z, wd1.w), ac1);
            }
            float xv = (ax0.x + ax0.y) + (ax1.x + ax1.y);
            float cv = leaky1((ac0.x + ac0.y) + (ac1.x + ac1.y) + sb[e]);
            outb[(size_t)j * NN] = xv + cv;
        }

        // transform row B, publish next buffers
        if (more) {
            transform_store(qa0, qa1, pa0, pa1, rs0, rs1,
                            &sqf[buf ^ 1][(2 * W + 1) * RP], lane, invN);
        }
        CP_WAIT0();
        __syncthreads();
    }
}

// ---------------- launch ----------------

extern "C" void kernel_launch(void* const* d_in, const int* in_sizes, int n_in,
                              void* d_out, int out_size)
{
    (void)in_sizes; (void)n_in; (void)out_size;
    const float* q     = (const float*)d_in[0];
    const float* k     = (const float*)d_in[1];
    const float* v     = (const float*)d_in[2];
    const float* pe1   = (const float*)d_in[3];
    const float* pe2   = (const float*)d_in[4];
    const float* scale = (const float*)d_in[5];
    const float* wconv = (const float*)d_in[6];
    const float* bconv = (const float*)d_in[7];
    float* out = (float*)d_out;

    cudaFuncSetAttribute(out_kernel, cudaFuncAttributeMaxDynamicSharedMemorySize, SMEM_BYTES);

    setup_kernel<<<64, 256>>>(scale);
    kv_kernel<<<dim3(NN / 64, BB), 256>>>(k, v, pe2);
    out_kernel<<<dim3(NN / 128, BB), 512, SMEM_BYTES>>>(q, v, pe1, wconv, bconv, out);
}

// round 6
// speedup vs baseline: 1.1158x; 1.1158x over previous
#include <cuda_runtime.h>
#include <math.h>
#include <stdint.h>

// Problem constants (per reference setup_inputs)
#define BB 8
#define NN 4096
#define CC 256
#define HN 8
#define DH 32
#define NPART 32   // kv partials per batch

// per-block kv partials [b][i][h][e][d] and reduced kv [b][h][e][d]
__device__ float g_kvp[BB * NPART * HN * DH * DH];
__device__ float g_kv[BB * HN * DH * DH];

// conv weight + bias in constant bank (uniform access -> LDC/LDCU port, not smem crossbar)
__constant__ float c_W[DH * DH];
__constant__ float c_b[DH];

// ---------------- helpers ----------------

__device__ __forceinline__ float2 ffma2(float2 a, float2 b, float2 c) {
    union U { float2 f; unsigned long long u; };
    U A, B_, C_, D;
    A.f = a; B_.f = b; C_.f = c;
    asm("fma.rn.f32x2 %0, %1, %2, %3;" : "=l"(D.u) : "l"(A.u), "l"(B_.u), "l"(C_.u));
    return D.f;
}

__device__ __forceinline__ float leaky1(float x) { return fmaxf(x, 0.1f * x); }

__device__ __forceinline__ float4 prep4(float4 a, float4 p, float4 rs) {
    float4 r;
    r.x = leaky1(a.x + p.x) * rs.x;
    r.y = leaky1(a.y + p.y) * rs.y;
    r.z = leaky1(a.z + p.z) * rs.z;
    r.w = leaky1(a.w + p.w) * rs.w;
    return r;
}

__device__ __forceinline__ float dot4(float4 a, float4 b) {
    return a.x * b.x + a.y * b.y + a.z * b.z + a.w * b.w;
}

__device__ __forceinline__ float4 cube4(float4 a) {
    float4 r;
    r.x = a.x * a.x * a.x; r.y = a.y * a.y * a.y;
    r.z = a.z * a.z * a.z; r.w = a.w * a.w * a.w;
    return r;
}

__device__ __forceinline__ float4 mul4s(float4 a, float s) {
    float4 r; r.x = a.x * s; r.y = a.y * s; r.z = a.z * s; r.w = a.w * s; return r;
}

__device__ __forceinline__ float4 rsoft4(const float* scale, int i) {
    float4 s = reinterpret_cast<const float4*>(scale)[i];
    float4 r;
    r.x = 1.0f / log1pf(expf(s.x));
    r.y = 1.0f / log1pf(expf(s.y));
    r.z = 1.0f / log1pf(expf(s.z));
    r.w = 1.0f / log1pf(expf(s.w));
    return r;
}

__device__ __forceinline__ void cp_async16(uint32_t saddr, const void* g) {
    asm volatile("cp.async.cg.shared.global [%0], [%1], 16;" :: "r"(saddr), "l"(g));
}
#define CP_COMMIT() asm volatile("cp.async.commit_group;")
#define CP_WAIT0()  asm volatile("cp.async.wait_group 0;")

__device__ __forceinline__ uint32_t s2u(const void* p) {
    return (uint32_t)__cvta_generic_to_shared(p);
}

// feature transform of one row held warp-wide in registers; writes focused row to smem
__device__ __forceinline__ void transform_store(
    float4 a0, float4 a1, float4 p0, float4 p1,
    float4 rs0, float4 rs1, float* qrow, int lane, float extra)
{
    float4 t0 = prep4(a0, p0, rs0);
    float4 t1 = prep4(a1, p1, rs1);
    float s2 = dot4(t0, t0) + dot4(t1, t1);
    float4 u0 = cube4(t0), u1 = cube4(t1);
    float s6 = dot4(u0, u0) + dot4(u1, u1);
#pragma unroll
    for (int m = 16; m; m >>= 1) {
        s2 += __shfl_xor_sync(0xffffffffu, s2, m);
        s6 += __shfl_xor_sync(0xffffffffu, s6, m);
    }
    const float f = (s6 > 0.f) ? sqrtf(s2 / s6) * extra : 0.f;
    reinterpret_cast<float4*>(qrow)[lane]      = mul4s(u0, f);
    reinterpret_cast<float4*>(qrow)[32 + lane] = mul4s(u1, f);
}

// ---------------- kernel 1: fused k-feature + kv partial accumulation (NO atomics) ----------------
// grid (32, B) = 256 blocks, 256 threads (8 warps). Warp w == head w.
// 128 rows per block as 16 groups of 8. v staged via cp.async, k+pe
// register-prefetched under the accumulate. Partials stored plain.

__global__ void __launch_bounds__(256, 2) kv_kernel(
    const float* __restrict__ k, const float* __restrict__ v,
    const float* __restrict__ pe2, const float* __restrict__ scale)
{
    __shared__ float ks[2][8 * 256];
    __shared__ float vsm[2][8 * 256];

    const int tid = threadIdx.x;
    const int w = tid >> 5;
    const int lane = tid & 31;
    const int b = blockIdx.y;
    const int n0 = blockIdx.x * 128;

    const float4 rs0 = rsoft4(scale, lane);
    const float4 rs1 = rsoft4(scale, 32 + lane);

    float2 acc[16];
#pragma unroll
    for (int j = 0; j < 16; j++) acc[j] = make_float2(0.f, 0.f);

    // prologue: cp.async v group 0, LDG k/pe group 0
#pragma unroll
    for (int i = 0; i < 2; i++) {
        int idx = i * 256 + tid;
        int r = idx >> 6, c = idx & 63;
        cp_async16(s2u(&vsm[0][r * 256 + c * 4]),
                   v + ((size_t)b * NN + n0 + r) * CC + c * 4);
    }
    CP_COMMIT();

    float4 ka0, ka1, pa0, pa1;
    {
        const int row = n0 + w;
        const float4* kg = reinterpret_cast<const float4*>(k + ((size_t)b * NN + row) * CC);
        const float4* pg = reinterpret_cast<const float4*>(pe2 + (size_t)row * CC);
        ka0 = kg[lane]; ka1 = kg[32 + lane];
        pa0 = pg[lane]; pa1 = pg[32 + lane];
    }

    for (int g = 0; g < 16; g++) {
        const int buf = g & 1;

        transform_store(ka0, ka1, pa0, pa1, rs0, rs1, &ks[buf][w * 256], lane, 1.0f);
        CP_WAIT0();
        __syncthreads();

        if (g < 15) {
            const int gn = g + 1;
#pragma unroll
            for (int i = 0; i < 2; i++) {
                int idx = i * 256 + tid;
                int r = idx >> 6, c = idx & 63;
                cp_async16(s2u(&vsm[buf ^ 1][r * 256 + c * 4]),
                           v + ((size_t)b * NN + n0 + gn * 8 + r) * CC + c * 4);
            }
            CP_COMMIT();
            const int row = n0 + gn * 8 + w;
            const float4* kg = reinterpret_cast<const float4*>(k + ((size_t)b * NN + row) * CC);
            const float4* pg = reinterpret_cast<const float4*>(pe2 + (size_t)row * CC);
            ka0 = kg[lane]; ka1 = kg[32 + lane];
            pa0 = pg[lane]; pa1 = pg[32 + lane];
        }

        // accumulate: thread owns d=lane for head w, all 32 e
#pragma unroll
        for (int r = 0; r < 8; r++) {
            const float kd = ks[buf][r * 256 + w * 32 + lane];
            const float2 k2 = make_float2(kd, kd);
            const float4* vp = reinterpret_cast<const float4*>(&vsm[buf][r * 256 + w * 32]);
#pragma unroll
            for (int j = 0; j < 8; j++) {
                float4 vv = vp[j];
                acc[2 * j]     = ffma2(k2, make_float2(vv.x, vv.y), acc[2 * j]);
                acc[2 * j + 1] = ffma2(k2, make_float2(vv.z, vv.w), acc[2 * j + 1]);
            }
        }
    }

    // plain coalesced store of this block's partial: [b][i][h][e][d]
    float* base = g_kvp + (((size_t)b * NPART + blockIdx.x) * HN + w) * (DH * DH);
#pragma unroll
    for (int j = 0; j < 16; j++) {
        base[(2 * j) * DH + lane]     = acc[j].x;
        base[(2 * j + 1) * DH + lane] = acc[j].y;
    }
}

// ---------------- kernel 1b: reduce the 32 partials ----------------
// 64 blocks x 256 threads, each thread sums one float4 across 32 partials.

__global__ void __launch_bounds__(256) reduce_kernel() {
    const int o = blockIdx.x * 256 + threadIdx.x;       // float4 index, 16384 total
    const int b = o >> 11;                              // 2048 float4 per batch
    const int r = o & 2047;
    const float4* src = reinterpret_cast<const float4*>(g_kvp) + (size_t)b * (NPART * 2048) + r;
    float4 s = make_float4(0.f, 0.f, 0.f, 0.f);
#pragma unroll
    for (int i = 0; i < NPART; i++) {
        float4 t = src[(size_t)i * 2048];
        s.x += t.x; s.y += t.y; s.z += t.z; s.w += t.w;
    }
    reinterpret_cast<float4*>(g_kv)[o] = s;
}

// ---------------- kernel 2: q-feature + x = qf@kv + leaky(v@W^T + b) ----------------
// grid (32, 8), 256 threads (warp = head), 2 CTAs/SM. 4 tiles of 32 rows per
// block. W + bias come from the constant bank (off the smem crossbar).

#define ROWPAD 260
#define SMEM_FLOATS (2 * 32 * ROWPAD + HN * DH * DH)
#define SMEM_BYTES (SMEM_FLOATS * 4)

__global__ void __launch_bounds__(256, 2) out_kernel(
    const float* __restrict__ q, const float* __restrict__ v,
    const float* __restrict__ pe1, const float* __restrict__ scale,
    float* __restrict__ out)
{
    extern __shared__ float sm[];
    float* sqf = sm;                       // 32*260
    float* svs = sm + 32 * ROWPAD;         // 32*260
    float* skv = sm + 2 * 32 * ROWPAD;     // 8192  [h][e][d]

    const int tid = threadIdx.x;
    const int w = tid >> 5;
    const int lane = tid & 31;
    const int b = blockIdx.y;

    // stage kv[b] once per block
    {
        const float4* kvg = reinterpret_cast<const float4*>(g_kv + (size_t)b * HN * DH * DH);
        float4* skv4 = reinterpret_cast<float4*>(skv);
#pragma unroll
        for (int i = 0; i < 8; i++) skv4[i * 256 + tid] = kvg[i * 256 + tid];
    }

    const float4 rs0 = rsoft4(scale, lane);
    const float4 rs1 = rsoft4(scale, 32 + lane);
    const float invN = 1.0f / (float)NN;

    for (int it = 0; it < 4; it++) {
        const int n0 = (blockIdx.x * 4 + it) * 32;

        __syncthreads();   // previous tile's readers done before rewriting smem

        // phase 1: q features + v staging (warp w handles rows w*4 .. w*4+3)
#pragma unroll
        for (int i = 0; i < 4; i++) {
            const int rl = w * 4 + i;
            const int row = n0 + rl;
            const float4* qg = reinterpret_cast<const float4*>(q + ((size_t)b * NN + row) * CC);
            const float4* vg = reinterpret_cast<const float4*>(v + ((size_t)b * NN + row) * CC);
            const float4* pg = reinterpret_cast<const float4*>(pe1 + (size_t)row * CC);

            float4 a0 = qg[lane], a1 = qg[32 + lane];
            float4 v0 = vg[lane], v1 = vg[32 + lane];
            float4 p0 = pg[lane], p1 = pg[32 + lane];

            transform_store(a0, a1, p0, p1, rs0, rs1, &sqf[rl * ROWPAD], lane, invN);
            float* vrow = svs + rl * ROWPAD;
            *reinterpret_cast<float4*>(vrow + lane * 4)       = v0;
            *reinterpret_cast<float4*>(vrow + 128 + lane * 4) = v1;
        }
        __syncthreads();

        // phase 2: per-lane row (n = n0+lane), per-warp head (h = w)
        float2 q2[16], v2[16];
        {
            const float4* qp = reinterpret_cast<const float4*>(sqf + lane * ROWPAD + w * DH);
            const float4* vp = reinterpret_cast<const float4*>(svs + lane * ROWPAD + w * DH);
#pragma unroll
            for (int j = 0; j < 8; j++) {
                float4 t = qp[j];
                q2[2 * j]     = make_float2(t.x, t.y);
                q2[2 * j + 1] = make_float2(t.z, t.w);
                float4 s = vp[j];
                v2[2 * j]     = make_float2(s.x, s.y);
                v2[2 * j + 1] = make_float2(s.z, s.w);
            }
        }

        const int n = n0 + lane;
        float* outb = out + ((size_t)b * CC + w * DH) * NN + n;

#pragma unroll 4
        for (int e = 0; e < DH; e++) {
            const float4* kp = reinterpret_cast<const float4*>(skv + w * (DH * DH) + e * DH);
            const float4* wp = reinterpret_cast<const float4*>(c_W + e * DH);   // constant bank
            float2 ax0 = make_float2(0.f, 0.f), ax1 = make_float2(0.f, 0.f);
            float2 ac0 = make_float2(0.f, 0.f), ac1 = make_float2(0.f, 0.f);
#pragma unroll
            for (int j = 0; j < 4; j++) {
                float4 kd0 = kp[2 * j], kd1 = kp[2 * j + 1];
                float4 wd0 = wp[2 * j], wd1 = wp[2 * j + 1];
                ax0 = ffma2(q2[4 * j],     make_float2(kd0.x, kd0.y), ax0);
                ax1 = ffma2(q2[4 * j + 1], make_float2(kd0.z, kd0.w), ax1);
                ax0 = ffma2(q2[4 * j + 2], make_float2(kd1.x, kd1.y), ax0);
                ax1 = ffma2(q2[4 * j + 3], make_float2(kd1.z, kd1.w), ax1);
                ac0 = ffma2(v2[4 * j],     make_float2(wd0.x, wd0.y), ac0);
                ac1 = ffma2(v2[4 * j + 1], make_float2(wd0.z, wd0.w), ac1);
                ac0 = ffma2(v2[4 * j + 2], make_float2(wd1.x, wd1.y), ac0);
                ac1 = ffma2(v2[4 * j + 3], make_float2(wd1.z, wd1.w), ac1);
            }
            float xv = (ax0.x + ax0.y) + (ax1.x + ax1.y);
            float cv = leaky1((ac0.x + ac0.y) + (ac1.x + ac1.y) + c_b[e]);
            outb[(size_t)e * NN] = xv + cv;
        }
    }
}

// ---------------- launch ----------------

extern "C" void kernel_launch(void* const* d_in, const int* in_sizes, int n_in,
                              void* d_out, int out_size)
{
    (void)in_sizes; (void)n_in; (void)out_size;
    const float* q     = (const float*)d_in[0];
    const float* k     = (const float*)d_in[1];
    const float* v     = (const float*)d_in[2];
    const float* pe1   = (const float*)d_in[3];
    const float* pe2   = (const float*)d_in[4];
    const float* scale = (const float*)d_in[5];
    const float* wconv = (const float*)d_in[6];
    const float* bconv = (const float*)d_in[7];
    float* out = (float*)d_out;

    cudaFuncSetAttribute(out_kernel, cudaFuncAttributeMaxDynamicSharedMemorySize, SMEM_BYTES);

    // async D2D copies into the constant bank (graph-capturable memcpy nodes)
    cudaMemcpyToSymbolAsync(c_W, wconv, DH * DH * sizeof(float), 0, cudaMemcpyDeviceToDevice);
    cudaMemcpyToSymbolAsync(c_b, bconv, DH * sizeof(float), 0, cudaMemcpyDeviceToDevice);

    kv_kernel<<<dim3(NPART, BB), 256>>>(k, v, pe2, scale);
    reduce_kernel<<<64, 256>>>();
    out_kernel<<<dim3(NN / 128, BB), 256, SMEM_BYTES>>>(q, v, pe1, scale, out);
}